// round 11
// baseline (speedup 1.0000x reference)
#include <cuda_runtime.h>
#include <cuda_fp16.h>
#include <math.h>
#include <stdint.h>

// Problem constants
#define B_SZ    512
#define N_SZ    256
#define N_ITERS 400
#define LAMBD   1.0f
#define KAPPA   0.1f

// 32x32 tiles over the 8x8 tile-grid upper triangle: 36 tiles per matrix.
#define NTILES 36
__constant__ int c_TA[NTILES] = {0,0,0,0,0,0,0,0, 1,1,1,1,1,1,1, 2,2,2,2,2,2,
                                 3,3,3,3,3, 4,4,4,4, 5,5,5, 6,6, 7};
__constant__ int c_TB[NTILES] = {0,1,2,3,4,5,6,7, 1,2,3,4,5,6,7, 2,3,4,5,6,7,
                                 3,4,5,6,7, 4,5,6,7, 5,6,7, 6,7, 7};

__device__ __forceinline__ int tri_idx(int a, int b) {  // a <= b
    return a * 8 - (a * (a - 1)) / 2 + (b - a);
}

// fp16 G tile store: 32 rows x 40 halves (80B stride)
#define TILE_STRIDE_B 80
#define TILE_BYTES    (32 * TILE_STRIDE_B)      // 2560
#define MAT_BYTES     (NTILES * TILE_BYTES)     // 92160
#define BATCH_BYTES   (2 * MAT_BYTES)           // 184320

__device__ unsigned char g_G16[(size_t)B_SZ * BATCH_BYTES];  // ~94 MB
__device__ float g_fro[2 * B_SZ];

// ---------------------------------------------------------------------------
// PTX helpers (base PTX only; no 'a'-gated instructions)
// ---------------------------------------------------------------------------
__device__ __forceinline__ uint32_t smem_u32(const void* p) {
    uint32_t a;
    asm("{ .reg .u64 t; cvta.to.shared.u64 t, %1; cvt.u32.u64 %0, t; }"
        : "=r"(a) : "l"(p));
    return a;
}
__device__ __forceinline__ void ldsm4(uint32_t& a0, uint32_t& a1, uint32_t& a2,
                                      uint32_t& a3, uint32_t addr) {
    asm volatile("ldmatrix.sync.aligned.m8n8.x4.shared.b16 {%0,%1,%2,%3}, [%4];"
                 : "=r"(a0), "=r"(a1), "=r"(a2), "=r"(a3) : "r"(addr));
}
__device__ __forceinline__ void ldsm4t(uint32_t& a0, uint32_t& a1, uint32_t& a2,
                                       uint32_t& a3, uint32_t addr) {
    asm volatile("ldmatrix.sync.aligned.m8n8.x4.trans.shared.b16 {%0,%1,%2,%3}, [%4];"
                 : "=r"(a0), "=r"(a1), "=r"(a2), "=r"(a3) : "r"(addr));
}
__device__ __forceinline__ void ldsm2t(uint32_t& r0, uint32_t& r1, uint32_t addr) {
    asm volatile("ldmatrix.sync.aligned.m8n8.x2.trans.shared.b16 {%0,%1}, [%2];"
                 : "=r"(r0), "=r"(r1) : "r"(addr));
}
__device__ __forceinline__ void mma16816(float* c, uint32_t a0, uint32_t a1,
                                         uint32_t a2, uint32_t a3,
                                         uint32_t b0, uint32_t b1) {
    asm volatile(
        "mma.sync.aligned.m16n8k16.row.col.f32.f16.f16.f32 "
        "{%0,%1,%2,%3}, {%4,%5,%6,%7}, {%8,%9}, {%0,%1,%2,%3};"
        : "+f"(c[0]), "+f"(c[1]), "+f"(c[2]), "+f"(c[3])
        : "r"(a0), "r"(a1), "r"(a2), "r"(a3), "r"(b0), "r"(b1));
}

// ---------------------------------------------------------------------------
// Kernel 1: batched SYRK via HMMA with split-fp16 inputs (unchanged from R8).
// ---------------------------------------------------------------------------
#define XS_STRIDE 528
#define XS_LBASE  (128 * XS_STRIDE)
#define XS_SCR    (2 * 128 * XS_STRIDE)
#define SYRK_SMEM (XS_SCR + 64)

__global__ __launch_bounds__(256, 1) void syrk16_kernel(const float* __restrict__ U,
                                                        const float* __restrict__ A) {
    extern __shared__ unsigned char sm[];
    const uint32_t smb = smem_u32(sm);
    const int mat = blockIdx.x >> 9;
    const int b = blockIdx.x & (B_SZ - 1);
    const float* __restrict__ X = (mat ? A : U) + (size_t)b * (N_SZ * N_SZ);
    const int t = threadIdx.x;
    const int lane = t & 31;
    const int w = t >> 5;

    const uint32_t lane_tr = (uint32_t)((lane & 7) + ((lane & 16) >> 1)) * XS_STRIDE
                           + (uint32_t)(lane & 8) * 2;
    const uint32_t laneB = (uint32_t)(lane & 15) * XS_STRIDE;

    float fro = 0.f;
    float acc[5][2][4][4];
    #pragma unroll
    for (int q = 0; q < 5; q++)
        #pragma unroll
        for (int mh = 0; mh < 2; mh++)
            #pragma unroll
            for (int nq = 0; nq < 4; nq++)
                #pragma unroll
                for (int e = 0; e < 4; e++) acc[q][mh][nq][e] = 0.f;

    #pragma unroll 1
    for (int ch = 0; ch < 2; ch++) {
        if (ch) __syncthreads();
        #pragma unroll 4
        for (int idx = t; idx < 128 * 128; idx += 256) {
            const int ir = idx >> 7;
            const int jp = idx & 127;
            const float2 f = *(const float2*)(X + (size_t)(128 * ch + ir) * N_SZ + 2 * jp);
            fro = fmaf(f.x, f.x, fro);
            fro = fmaf(f.y, f.y, fro);
            const __half hx = __float2half_rn(f.x);
            const __half hy = __float2half_rn(f.y);
            const __half lx = __float2half_rn(f.x - __half2float(hx));
            const __half ly = __float2half_rn(f.y - __half2float(hy));
            *(__half2*)(sm + ir * XS_STRIDE + jp * 4) = __halves2half2(hx, hy);
            *(__half2*)(sm + XS_LBASE + ir * XS_STRIDE + jp * 4) = __halves2half2(lx, ly);
        }
        __syncthreads();

        #pragma unroll
        for (int q = 0; q < 5; q++) {
            const int tix = w + 8 * q;
            if (tix < NTILES) {
                const int a0 = c_TA[tix], b0 = c_TB[tix];
                const uint32_t acol = smb + (uint32_t)(a0 * 32) * 2 + lane_tr;
                const uint32_t bcol = smb + (uint32_t)(b0 * 32) * 2 + laneB;
                #pragma unroll
                for (int kc = 0; kc < 8; kc++) {
                    const uint32_t ro = (uint32_t)(kc * 16) * XS_STRIDE;
                    uint32_t AH[2][4], AL[2][4];
                    #pragma unroll
                    for (int mh = 0; mh < 2; mh++) {
                        const uint32_t ao = acol + ro + (uint32_t)(mh * 16) * 2;
                        ldsm4t(AH[mh][0], AH[mh][1], AH[mh][2], AH[mh][3], ao);
                        ldsm4t(AL[mh][0], AL[mh][1], AL[mh][2], AL[mh][3],
                               ao + XS_LBASE);
                    }
                    #pragma unroll
                    for (int nq = 0; nq < 4; nq++) {
                        const uint32_t bo = bcol + ro + (uint32_t)(nq * 8) * 2;
                        uint32_t bh0, bh1, bl0, bl1;
                        ldsm2t(bh0, bh1, bo);
                        ldsm2t(bl0, bl1, bo + XS_LBASE);
                        #pragma unroll
                        for (int mh = 0; mh < 2; mh++) {
                            float* c = acc[q][mh][nq];
                            mma16816(c, AH[mh][0], AH[mh][1], AH[mh][2], AH[mh][3],
                                     bh0, bh1);
                            mma16816(c, AH[mh][0], AH[mh][1], AH[mh][2], AH[mh][3],
                                     bl0, bl1);
                            mma16816(c, AL[mh][0], AL[mh][1], AL[mh][2], AL[mh][3],
                                     bh0, bh1);
                        }
                    }
                }
            }
        }
    }

    unsigned char* gb = g_G16 + (size_t)b * BATCH_BYTES + (size_t)mat * MAT_BYTES;
    #pragma unroll
    for (int q = 0; q < 5; q++) {
        const int tix = w + 8 * q;
        if (tix < NTILES) {
            #pragma unroll
            for (int mh = 0; mh < 2; mh++)
                #pragma unroll
                for (int nq = 0; nq < 4; nq++) {
                    const float* c = acc[q][mh][nq];
                    const uint32_t o = (uint32_t)tix * TILE_BYTES
                        + (uint32_t)(mh * 16 + (lane >> 2)) * TILE_STRIDE_B
                        + (uint32_t)(nq * 4 + (lane & 3)) * 4;
                    *(__half2*)(gb + o) =
                        __halves2half2(__float2half_rn(c[0]), __float2half_rn(c[1]));
                    *(__half2*)(gb + o + 8 * TILE_STRIDE_B) =
                        __halves2half2(__float2half_rn(c[2]), __float2half_rn(c[3]));
                }
        }
    }

    #pragma unroll
    for (int o = 16; o; o >>= 1) fro += __shfl_xor_sync(0xFFFFFFFFu, fro, o);
    float* scr = (float*)(sm + XS_SCR);
    if (lane == 0) scr[w] = fro;
    __syncthreads();
    if (t == 0) {
        float s = 0.f;
        #pragma unroll
        for (int qq = 0; qq < 8; qq++) s += scr[qq];
        g_fro[mat * B_SZ + b] = s;
    }
}

// ---------------------------------------------------------------------------
// Kernel 2: 400-iteration PGD. 256 threads = 8 warps. SPLIT ACCUMULATORS:
// each logical output accumulator is an even/odd pair keyed on kslice parity
// -> 8 independent chains of 8 serial HMMAs (was 4x16) to halve exposed
// tensor latency. 4 register-resident k-bands, 4 streamed. Transposed y,
// one barrier/iter, warm Newton, replicated projection.
// ---------------------------------------------------------------------------
#define SM_WPRIV 0                               // 8 warps x 512 B
#define SM_Y1    4096                            // [2][256] f32 transposed
#define SM_Y2    6144
#define SM_PROD  8192
#define SM_TILES 10240
#define SM_TOTAL (SM_TILES + BATCH_BYTES)        // 194560

__global__ __launch_bounds__(256, 1) void pgd_mma_kernel(const float* __restrict__ mu,
                                                         float* __restrict__ out) {
    extern __shared__ unsigned char sm[];
    const uint32_t smb = smem_u32(sm);
    const int b = blockIdx.x;
    const int t = threadIdx.x;
    const int lane = t & 31;
    const int r = t >> 5;                   // warp id == output band

    // ---- init: raw copy of both fp16 triangles ----
    {
        const uint4* src = (const uint4*)(g_G16 + (size_t)b * BATCH_BYTES);
        uint4* dst = (uint4*)(sm + SM_TILES);
        #pragma unroll 4
        for (int i = t; i < BATCH_BYTES / 16; i += 256) dst[i] = src[i];
    }

    const uint32_t t1base = smb + SM_TILES;
    const uint32_t t2base = smb + SM_TILES + MAT_BYTES;
    const uint32_t wpriv = smb + SM_WPRIV + (uint32_t)r * 512;

    const uint32_t lane_nt = (uint32_t)((lane & 7) + (lane & 8)) * TILE_STRIDE_B
                           + (uint32_t)((lane & 16) >> 1) * 2;
    const uint32_t lane_tr = (uint32_t)((lane & 7) + ((lane & 16) >> 1)) * TILE_STRIDE_B
                           + (uint32_t)(lane & 8) * 2;

    const float step = 1.0f / (LAMBD * g_fro[b] + KAPPA * sqrtf(g_fro[B_SZ + b]) + 1.0f);

    __syncthreads();

    // ---- preload k-bands 0..3 into registers (128 frag regs) ----
    uint32_t fr[2][4][2][2][4];
    #pragma unroll
    for (int m = 0; m < 2; m++) {
        const uint32_t tb = m ? t2base : t1base;
        #pragma unroll
        for (int bb = 0; bb < 4; bb++) {
            const bool tr = (bb < r);
            const int aa = tr ? bb : r;
            const int bn = tr ? r : bb;
            const uint32_t tile = tb + (uint32_t)tri_idx(aa, bn) * TILE_BYTES;
            #pragma unroll
            for (int ks = 0; ks < 2; ks++) {
                if (tr) {
                    const uint32_t o = (uint32_t)ks * (16 * TILE_STRIDE_B) + lane_tr;
                    ldsm4t(fr[m][bb][ks][0][0], fr[m][bb][ks][0][1],
                           fr[m][bb][ks][0][2], fr[m][bb][ks][0][3], tile + o);
                    ldsm4t(fr[m][bb][ks][1][0], fr[m][bb][ks][1][1],
                           fr[m][bb][ks][1][2], fr[m][bb][ks][1][3], tile + o + 32);
                } else {
                    const uint32_t o = (uint32_t)ks * 32 + lane_nt;
                    ldsm4(fr[m][bb][ks][0][0], fr[m][bb][ks][0][1],
                          fr[m][bb][ks][0][2], fr[m][bb][ks][0][3], tile + o);
                    ldsm4(fr[m][bb][ks][1][0], fr[m][bb][ks][1][1],
                          fr[m][bb][ks][1][2], fr[m][bb][ks][1][3],
                          tile + o + 16 * TILE_STRIDE_B);
                }
            }
        }
    }

    // ---- replicated solver state (identical in every warp) ----
    float wv[8], mu_r[8];
    float tau = 0.0f;
    #pragma unroll
    for (int k = 0; k < 8; k++) {
        wv[k] = 1.0f / (float)N_SZ;
        mu_r[k] = mu[(size_t)b * N_SZ + lane + (k << 5)];
        const __half h = __float2half_rn(wv[k]);
        asm volatile("st.shared.u16 [%0], %1;"
                     :: "r"(wpriv + (uint32_t)(lane + (k << 5)) * 2),
                        "h"(__half_as_ushort(h)) : "memory");
    }
    __syncwarp();
    __syncthreads();

    #pragma unroll 1
    for (int it = 0; it < N_ITERS; it++) {
        const uint32_t buf = (uint32_t)(it & 1);
        float* const y1s = (float*)(sm + SM_Y1 + buf * 1024);
        float* const y2s = (float*)(sm + SM_Y2 + buf * 1024);
        float* const prods = (float*)(sm + SM_PROD + buf * 32);

        // even (ks=0) and odd (ks=1) accumulator pairs -> 8 chains of 8 MMAs
        float c1Ae[4] = {0,0,0,0}, c1Ao[4] = {0,0,0,0};
        float c1Be[4] = {0,0,0,0}, c1Bo[4] = {0,0,0,0};
        float c2Ae[4] = {0,0,0,0}, c2Ao[4] = {0,0,0,0};
        float c2Be[4] = {0,0,0,0}, c2Bo[4] = {0,0,0,0};

        // ---- k-bands 0..3: register-resident fragments ----
        #pragma unroll
        for (int bb = 0; bb < 4; bb++) {
            #pragma unroll
            for (int ks = 0; ks < 2; ks++) {
                uint32_t b0, b1;
                const uint32_t waddr = wpriv + (uint32_t)(bb * 64 + ks * 32)
                                     + (uint32_t)(lane & 3) * 4;
                asm volatile("ld.shared.b32 %0, [%1];" : "=r"(b0) : "r"(waddr));
                asm volatile("ld.shared.b32 %0, [%1];" : "=r"(b1) : "r"(waddr + 16));
                if (lane >= 4) { b0 = 0u; b1 = 0u; }

                float* d1A = ks ? c1Ao : c1Ae;
                float* d1B = ks ? c1Bo : c1Be;
                float* d2A = ks ? c2Ao : c2Ae;
                float* d2B = ks ? c2Bo : c2Be;
                mma16816(d1A, fr[0][bb][ks][0][0], fr[0][bb][ks][0][1],
                              fr[0][bb][ks][0][2], fr[0][bb][ks][0][3], b0, b1);
                mma16816(d1B, fr[0][bb][ks][1][0], fr[0][bb][ks][1][1],
                              fr[0][bb][ks][1][2], fr[0][bb][ks][1][3], b0, b1);
                mma16816(d2A, fr[1][bb][ks][0][0], fr[1][bb][ks][0][1],
                              fr[1][bb][ks][0][2], fr[1][bb][ks][0][3], b0, b1);
                mma16816(d2B, fr[1][bb][ks][1][0], fr[1][bb][ks][1][1],
                              fr[1][bb][ks][1][2], fr[1][bb][ks][1][3], b0, b1);
            }
        }

        // ---- k-bands 4..7: batched LDSM (4) then MMA (4) per (band,kslice) ----
        #pragma unroll
        for (int bb = 4; bb < 8; bb++) {
            const bool tr = (bb < r);
            const int aa = tr ? bb : r;
            const int bn = tr ? r : bb;
            const uint32_t toff = (uint32_t)tri_idx(aa, bn) * TILE_BYTES;
            const uint32_t tile1 = t1base + toff;
            const uint32_t tile2 = t2base + toff;
            #pragma unroll
            for (int ks = 0; ks < 2; ks++) {
                uint32_t b0, b1;
                const uint32_t waddr = wpriv + (uint32_t)(bb * 64 + ks * 32)
                                     + (uint32_t)(lane & 3) * 4;
                asm volatile("ld.shared.b32 %0, [%1];" : "=r"(b0) : "r"(waddr));
                asm volatile("ld.shared.b32 %0, [%1];" : "=r"(b1) : "r"(waddr + 16));
                if (lane >= 4) { b0 = 0u; b1 = 0u; }

                uint32_t sA[4][4];
                if (tr) {
                    const uint32_t o = (uint32_t)ks * (16 * TILE_STRIDE_B) + lane_tr;
                    ldsm4t(sA[0][0], sA[0][1], sA[0][2], sA[0][3], tile1 + o);
                    ldsm4t(sA[1][0], sA[1][1], sA[1][2], sA[1][3], tile1 + o + 32);
                    ldsm4t(sA[2][0], sA[2][1], sA[2][2], sA[2][3], tile2 + o);
                    ldsm4t(sA[3][0], sA[3][1], sA[3][2], sA[3][3], tile2 + o + 32);
                } else {
                    const uint32_t o = (uint32_t)ks * 32 + lane_nt;
                    ldsm4(sA[0][0], sA[0][1], sA[0][2], sA[0][3], tile1 + o);
                    ldsm4(sA[1][0], sA[1][1], sA[1][2], sA[1][3],
                          tile1 + o + 16 * TILE_STRIDE_B);
                    ldsm4(sA[2][0], sA[2][1], sA[2][2], sA[2][3], tile2 + o);
                    ldsm4(sA[3][0], sA[3][1], sA[3][2], sA[3][3],
                          tile2 + o + 16 * TILE_STRIDE_B);
                }
                float* d1A = ks ? c1Ao : c1Ae;
                float* d1B = ks ? c1Bo : c1Be;
                float* d2A = ks ? c2Ao : c2Ae;
                float* d2B = ks ? c2Bo : c2Be;
                mma16816(d1A, sA[0][0], sA[0][1], sA[0][2], sA[0][3], b0, b1);
                mma16816(d1B, sA[1][0], sA[1][1], sA[1][2], sA[1][3], b0, b1);
                mma16816(d2A, sA[2][0], sA[2][1], sA[2][2], sA[2][3], b0, b1);
                mma16816(d2B, sA[3][0], sA[3][1], sA[3][2], sA[3][3], b0, b1);
            }
        }

        // ---- merge even/odd chains (only elements 0 and 2 are used) ----
        const float c1A0 = c1Ae[0] + c1Ao[0], c1A2 = c1Ae[2] + c1Ao[2];
        const float c1B0 = c1Be[0] + c1Bo[0], c1B2 = c1Be[2] + c1Bo[2];
        const float c2A0 = c2Ae[0] + c2Ao[0], c2A2 = c2Ae[2] + c2Ao[2];
        const float c2B0 = c2Be[0] + c2Bo[0], c2B2 = c2Be[2] + c2Bo[2];

        // ---- store y bands TRANSPOSED: y[c] -> float idx (c&31)*8 + (c>>5)
        const int g = lane >> 2;
        if ((lane & 3) == 0) {
            y1s[g * 8 + r]        = c1A0;
            y1s[(g + 8) * 8 + r]  = c1A2;
            y1s[(g + 16) * 8 + r] = c1B0;
            y1s[(g + 24) * 8 + r] = c1B2;
            y2s[g * 8 + r]        = c2A0;
            y2s[(g + 8) * 8 + r]  = c2A2;
            y2s[(g + 16) * 8 + r] = c2B0;
            y2s[(g + 24) * 8 + r] = c2B2;
        }
        {
            const float wg0 = __shfl_sync(0xFFFFFFFFu, wv[r], g);
            const float wg1 = __shfl_sync(0xFFFFFFFFu, wv[r], g + 8);
            const float wg2 = __shfl_sync(0xFFFFFFFFu, wv[r], g + 16);
            const float wg3 = __shfl_sync(0xFFFFFFFFu, wv[r], g + 24);
            float p = c2A0 * wg0 + c2A2 * wg1 + c2B0 * wg2 + c2B2 * wg3;
            p += __shfl_xor_sync(0xFFFFFFFFu, p, 4);
            p += __shfl_xor_sync(0xFFFFFFFFu, p, 8);
            p += __shfl_xor_sync(0xFFFFFFFFu, p, 16);
            if (lane == 0) prods[r] = p;
        }
        __syncthreads();   // the ONLY barrier per iteration

        // ---- replicated projection (vectorized reads) ----
        float4 pv0 = *(const float4*)prods;
        float4 pv1 = *(const float4*)(prods + 4);
        const float pr = ((pv0.x + pv0.y) + (pv0.z + pv0.w))
                       + ((pv1.x + pv1.y) + (pv1.z + pv1.w));
        const float nrm = sqrtf(fmaxf(pr, 1e-12f));
        const float kin = KAPPA / nrm;

        float y1v[8], y2v[8];
        {
            const float4 a0 = *(const float4*)(y1s + lane * 8);
            const float4 a1 = *(const float4*)(y1s + lane * 8 + 4);
            const float4 b0v = *(const float4*)(y2s + lane * 8);
            const float4 b1v = *(const float4*)(y2s + lane * 8 + 4);
            y1v[0] = a0.x; y1v[1] = a0.y; y1v[2] = a0.z; y1v[3] = a0.w;
            y1v[4] = a1.x; y1v[5] = a1.y; y1v[6] = a1.z; y1v[7] = a1.w;
            y2v[0] = b0v.x; y2v[1] = b0v.y; y2v[2] = b0v.z; y2v[3] = b0v.w;
            y2v[4] = b1v.x; y2v[5] = b1v.y; y2v[6] = b1v.z; y2v[7] = b1v.w;
        }

        float v[8];
        #pragma unroll
        for (int k = 0; k < 8; k++) {
            const float grad = -mu_r[k] + LAMBD * y1v[k] + kin * y2v[k];
            v[k] = wv[k] - step * grad;
        }

        // Warm-started Newton on f(tau) = sum(relu(v-tau)) - 1.
        float tt = tau;
        bool fb = false;
        for (int ni = 0; ni < 12; ni++) {
            float s = 0.f;
            int cnt = 0;
            #pragma unroll
            for (int k = 0; k < 8; k++) {
                const float d = v[k] - tt;
                if (d > 0.f) { s += d; cnt++; }
            }
            cnt = __reduce_add_sync(0xFFFFFFFFu, cnt);
            #pragma unroll
            for (int o = 16; o; o >>= 1)
                s += __shfl_xor_sync(0xFFFFFFFFu, s, o);
            if (cnt == 0) {
                if (fb) break;
                fb = true;
                float S = 0.f;
                #pragma unroll
                for (int k = 0; k < 8; k++) S += v[k];
                #pragma unroll
                for (int o = 16; o; o >>= 1)
                    S += __shfl_xor_sync(0xFFFFFFFFu, S, o);
                tt = (S - 1.0f) * (1.0f / (float)N_SZ);
                continue;
            }
            const float delta = (s - 1.0f) / (float)cnt;
            tt += delta;
            if (fabsf(delta) <= 1e-10f) break;
        }
        tau = tt;

        #pragma unroll
        for (int k = 0; k < 8; k++) {
            wv[k] = fmaxf(v[k] - tau, 0.f);
            const __half h = __float2half_rn(wv[k]);
            asm volatile("st.shared.u16 [%0], %1;"
                         :: "r"(wpriv + (uint32_t)(lane + (k << 5)) * 2),
                            "h"(__half_as_ushort(h)) : "memory");
        }
        __syncwarp();
    }

    // ---- final clamp + renormalize (warp 0 writes) ----
    if (r == 0) {
        float s = 0.f;
        #pragma unroll
        for (int k = 0; k < 8; k++) { wv[k] = fmaxf(wv[k], 0.f); s += wv[k]; }
        #pragma unroll
        for (int o = 16; o; o >>= 1) s += __shfl_xor_sync(0xFFFFFFFFu, s, o);
        const float inv = 1.0f / (s + 1e-12f);
        #pragma unroll
        for (int k = 0; k < 8; k++)
            out[(size_t)b * N_SZ + lane + (k << 5)] = wv[k] * inv;
    }
}

// ---------------------------------------------------------------------------
// Launcher
// ---------------------------------------------------------------------------
extern "C" void kernel_launch(void* const* d_in, const int* in_sizes, int n_in,
                              void* d_out, int out_size) {
    const float* mu = (const float*)d_in[0];
    const float* U  = (const float*)d_in[1];
    const float* A  = (const float*)d_in[2];
    float* out = (float*)d_out;

    cudaFuncSetAttribute(syrk16_kernel, cudaFuncAttributeMaxDynamicSharedMemorySize,
                         SYRK_SMEM);
    cudaFuncSetAttribute(pgd_mma_kernel, cudaFuncAttributeMaxDynamicSharedMemorySize,
                         SM_TOTAL);

    syrk16_kernel<<<2 * B_SZ, 256, SYRK_SMEM>>>(U, A);
    pgd_mma_kernel<<<B_SZ, 256, SM_TOTAL>>>(mu, out);
}

// round 12
// speedup vs baseline: 1.0599x; 1.0599x over previous
#include <cuda_runtime.h>
#include <cuda_fp16.h>
#include <math.h>
#include <stdint.h>

// Problem constants
#define B_SZ    512
#define N_SZ    256
#define N_ITERS 400
#define LAMBD   1.0f
#define KAPPA   0.1f

// 32x32 tiles over the 8x8 tile-grid upper triangle: 36 tiles per matrix.
#define NTILES 36
__constant__ int c_TA[NTILES] = {0,0,0,0,0,0,0,0, 1,1,1,1,1,1,1, 2,2,2,2,2,2,
                                 3,3,3,3,3, 4,4,4,4, 5,5,5, 6,6, 7};
__constant__ int c_TB[NTILES] = {0,1,2,3,4,5,6,7, 1,2,3,4,5,6,7, 2,3,4,5,6,7,
                                 3,4,5,6,7, 4,5,6,7, 5,6,7, 6,7, 7};

__device__ __forceinline__ int tri_idx(int a, int b) {  // a <= b
    return a * 8 - (a * (a - 1)) / 2 + (b - a);
}

// fp16 G tile store: 32 rows x 40 halves (80B stride)
#define TILE_STRIDE_B 80
#define TILE_BYTES    (32 * TILE_STRIDE_B)      // 2560
#define MAT_BYTES     (NTILES * TILE_BYTES)     // 92160
#define BATCH_BYTES   (2 * MAT_BYTES)           // 184320

__device__ unsigned char g_G16[(size_t)B_SZ * BATCH_BYTES];  // ~94 MB
__device__ float g_fro[2 * B_SZ];

// ---------------------------------------------------------------------------
// PTX helpers (base PTX only; no 'a'-gated instructions)
// ---------------------------------------------------------------------------
__device__ __forceinline__ uint32_t smem_u32(const void* p) {
    uint32_t a;
    asm("{ .reg .u64 t; cvta.to.shared.u64 t, %1; cvt.u32.u64 %0, t; }"
        : "=r"(a) : "l"(p));
    return a;
}
__device__ __forceinline__ void ldsm4(uint32_t& a0, uint32_t& a1, uint32_t& a2,
                                      uint32_t& a3, uint32_t addr) {
    asm volatile("ldmatrix.sync.aligned.m8n8.x4.shared.b16 {%0,%1,%2,%3}, [%4];"
                 : "=r"(a0), "=r"(a1), "=r"(a2), "=r"(a3) : "r"(addr));
}
__device__ __forceinline__ void ldsm4t(uint32_t& a0, uint32_t& a1, uint32_t& a2,
                                       uint32_t& a3, uint32_t addr) {
    asm volatile("ldmatrix.sync.aligned.m8n8.x4.trans.shared.b16 {%0,%1,%2,%3}, [%4];"
                 : "=r"(a0), "=r"(a1), "=r"(a2), "=r"(a3) : "r"(addr));
}
__device__ __forceinline__ void ldsm2t(uint32_t& r0, uint32_t& r1, uint32_t addr) {
    asm volatile("ldmatrix.sync.aligned.m8n8.x2.trans.shared.b16 {%0,%1}, [%2];"
                 : "=r"(r0), "=r"(r1) : "r"(addr));
}
// fp32-accumulator MMA
__device__ __forceinline__ void mma16816(float* c, uint32_t a0, uint32_t a1,
                                         uint32_t a2, uint32_t a3,
                                         uint32_t b0, uint32_t b1) {
    asm volatile(
        "mma.sync.aligned.m16n8k16.row.col.f32.f16.f16.f32 "
        "{%0,%1,%2,%3}, {%4,%5,%6,%7}, {%8,%9}, {%0,%1,%2,%3};"
        : "+f"(c[0]), "+f"(c[1]), "+f"(c[2]), "+f"(c[3])
        : "r"(a0), "r"(a1), "r"(a2), "r"(a3), "r"(b0), "r"(b1));
}
// fp16-accumulator MMA (2x f16x2 accumulator regs)
__device__ __forceinline__ void mma16816h(uint32_t* c, uint32_t a0, uint32_t a1,
                                          uint32_t a2, uint32_t a3,
                                          uint32_t b0, uint32_t b1) {
    asm volatile(
        "mma.sync.aligned.m16n8k16.row.col.f16.f16.f16.f16 "
        "{%0,%1}, {%2,%3,%4,%5}, {%6,%7}, {%0,%1};"
        : "+r"(c[0]), "+r"(c[1])
        : "r"(a0), "r"(a1), "r"(a2), "r"(a3), "r"(b0), "r"(b1));
}

// ---------------------------------------------------------------------------
// Kernel 1: batched SYRK via HMMA with split-fp16 inputs (unchanged from R8).
// ---------------------------------------------------------------------------
#define XS_STRIDE 528
#define XS_LBASE  (128 * XS_STRIDE)
#define XS_SCR    (2 * 128 * XS_STRIDE)
#define SYRK_SMEM (XS_SCR + 64)

__global__ __launch_bounds__(256, 1) void syrk16_kernel(const float* __restrict__ U,
                                                        const float* __restrict__ A) {
    extern __shared__ unsigned char sm[];
    const uint32_t smb = smem_u32(sm);
    const int mat = blockIdx.x >> 9;
    const int b = blockIdx.x & (B_SZ - 1);
    const float* __restrict__ X = (mat ? A : U) + (size_t)b * (N_SZ * N_SZ);
    const int t = threadIdx.x;
    const int lane = t & 31;
    const int w = t >> 5;

    const uint32_t lane_tr = (uint32_t)((lane & 7) + ((lane & 16) >> 1)) * XS_STRIDE
                           + (uint32_t)(lane & 8) * 2;
    const uint32_t laneB = (uint32_t)(lane & 15) * XS_STRIDE;

    float fro = 0.f;
    float acc[5][2][4][4];
    #pragma unroll
    for (int q = 0; q < 5; q++)
        #pragma unroll
        for (int mh = 0; mh < 2; mh++)
            #pragma unroll
            for (int nq = 0; nq < 4; nq++)
                #pragma unroll
                for (int e = 0; e < 4; e++) acc[q][mh][nq][e] = 0.f;

    #pragma unroll 1
    for (int ch = 0; ch < 2; ch++) {
        if (ch) __syncthreads();
        #pragma unroll 4
        for (int idx = t; idx < 128 * 128; idx += 256) {
            const int ir = idx >> 7;
            const int jp = idx & 127;
            const float2 f = *(const float2*)(X + (size_t)(128 * ch + ir) * N_SZ + 2 * jp);
            fro = fmaf(f.x, f.x, fro);
            fro = fmaf(f.y, f.y, fro);
            const __half hx = __float2half_rn(f.x);
            const __half hy = __float2half_rn(f.y);
            const __half lx = __float2half_rn(f.x - __half2float(hx));
            const __half ly = __float2half_rn(f.y - __half2float(hy));
            *(__half2*)(sm + ir * XS_STRIDE + jp * 4) = __halves2half2(hx, hy);
            *(__half2*)(sm + XS_LBASE + ir * XS_STRIDE + jp * 4) = __halves2half2(lx, ly);
        }
        __syncthreads();

        #pragma unroll
        for (int q = 0; q < 5; q++) {
            const int tix = w + 8 * q;
            if (tix < NTILES) {
                const int a0 = c_TA[tix], b0 = c_TB[tix];
                const uint32_t acol = smb + (uint32_t)(a0 * 32) * 2 + lane_tr;
                const uint32_t bcol = smb + (uint32_t)(b0 * 32) * 2 + laneB;
                #pragma unroll
                for (int kc = 0; kc < 8; kc++) {
                    const uint32_t ro = (uint32_t)(kc * 16) * XS_STRIDE;
                    uint32_t AH[2][4], AL[2][4];
                    #pragma unroll
                    for (int mh = 0; mh < 2; mh++) {
                        const uint32_t ao = acol + ro + (uint32_t)(mh * 16) * 2;
                        ldsm4t(AH[mh][0], AH[mh][1], AH[mh][2], AH[mh][3], ao);
                        ldsm4t(AL[mh][0], AL[mh][1], AL[mh][2], AL[mh][3],
                               ao + XS_LBASE);
                    }
                    #pragma unroll
                    for (int nq = 0; nq < 4; nq++) {
                        const uint32_t bo = bcol + ro + (uint32_t)(nq * 8) * 2;
                        uint32_t bh0, bh1, bl0, bl1;
                        ldsm2t(bh0, bh1, bo);
                        ldsm2t(bl0, bl1, bo + XS_LBASE);
                        #pragma unroll
                        for (int mh = 0; mh < 2; mh++) {
                            float* c = acc[q][mh][nq];
                            mma16816(c, AH[mh][0], AH[mh][1], AH[mh][2], AH[mh][3],
                                     bh0, bh1);
                            mma16816(c, AH[mh][0], AH[mh][1], AH[mh][2], AH[mh][3],
                                     bl0, bl1);
                            mma16816(c, AL[mh][0], AL[mh][1], AL[mh][2], AL[mh][3],
                                     bh0, bh1);
                        }
                    }
                }
            }
        }
    }

    unsigned char* gb = g_G16 + (size_t)b * BATCH_BYTES + (size_t)mat * MAT_BYTES;
    #pragma unroll
    for (int q = 0; q < 5; q++) {
        const int tix = w + 8 * q;
        if (tix < NTILES) {
            #pragma unroll
            for (int mh = 0; mh < 2; mh++)
                #pragma unroll
                for (int nq = 0; nq < 4; nq++) {
                    const float* c = acc[q][mh][nq];
                    const uint32_t o = (uint32_t)tix * TILE_BYTES
                        + (uint32_t)(mh * 16 + (lane >> 2)) * TILE_STRIDE_B
                        + (uint32_t)(nq * 4 + (lane & 3)) * 4;
                    *(__half2*)(gb + o) =
                        __halves2half2(__float2half_rn(c[0]), __float2half_rn(c[1]));
                    *(__half2*)(gb + o + 8 * TILE_STRIDE_B) =
                        __halves2half2(__float2half_rn(c[2]), __float2half_rn(c[3]));
                }
        }
    }

    #pragma unroll
    for (int o = 16; o; o >>= 1) fro += __shfl_xor_sync(0xFFFFFFFFu, fro, o);
    float* scr = (float*)(sm + XS_SCR);
    if (lane == 0) scr[w] = fro;
    __syncthreads();
    if (t == 0) {
        float s = 0.f;
        #pragma unroll
        for (int qq = 0; qq < 8; qq++) s += scr[qq];
        g_fro[mat * B_SZ + b] = s;
    }
}

// ---------------------------------------------------------------------------
// Kernel 2: 400-iteration PGD. R10 base (8 warps, 5 reg bands, single chains,
// transposed y) + two changes:
//   (a) G2 matvec uses fp16 accumulators (rt probe / 2x if HMMA rt-bound)
//   (b) w stored in b-frag-packed layout: b0,b1 fetched by ONE ld.shared.v2
// ---------------------------------------------------------------------------
#define SM_WPRIV 0                               // 8 warps x 512 B
#define SM_Y1    4096                            // [2][256] f32 transposed
#define SM_Y2    6144
#define SM_PROD  8192
#define SM_TILES 10240
#define SM_TOTAL (SM_TILES + BATCH_BYTES)        // 194560

__global__ __launch_bounds__(256, 1) void pgd_mma_kernel(const float* __restrict__ mu,
                                                         float* __restrict__ out) {
    extern __shared__ unsigned char sm[];
    const uint32_t smb = smem_u32(sm);
    const int b = blockIdx.x;
    const int t = threadIdx.x;
    const int lane = t & 31;
    const int r = t >> 5;                   // warp id == output band

    // ---- init: raw copy of both fp16 triangles ----
    {
        const uint4* src = (const uint4*)(g_G16 + (size_t)b * BATCH_BYTES);
        uint4* dst = (uint4*)(sm + SM_TILES);
        #pragma unroll 4
        for (int i = t; i < BATCH_BYTES / 16; i += 256) dst[i] = src[i];
    }

    const uint32_t t1base = smb + SM_TILES;
    const uint32_t t2base = smb + SM_TILES + MAT_BYTES;
    const uint32_t wpriv = smb + SM_WPRIV + (uint32_t)r * 512;

    const uint32_t lane_nt = (uint32_t)((lane & 7) + (lane & 8)) * TILE_STRIDE_B
                           + (uint32_t)((lane & 16) >> 1) * 2;
    const uint32_t lane_tr = (uint32_t)((lane & 7) + ((lane & 16) >> 1)) * TILE_STRIDE_B
                           + (uint32_t)(lane & 8) * 2;

    // packed-w writer offset for this lane: group (ks,j) slot within 64B/k
    // halves group g=(bb*8+ks*4+j): {w[bb*32+ks*16+2j], +1, +8, +9}
    const int pw = lane & 15;
    const uint32_t lane_woff = (uint32_t)(((lane >> 4) & 1) * 4 + ((pw >> 1) & 3)) * 8
                             + (uint32_t)((((pw >> 3) << 1) | (pw & 1)) * 2);

    const float step = 1.0f / (LAMBD * g_fro[b] + KAPPA * sqrtf(g_fro[B_SZ + b]) + 1.0f);

    __syncthreads();

    // ---- preload k-bands 0..4 into registers (160 frag regs) ----
    uint32_t fr[2][5][2][2][4];
    #pragma unroll
    for (int m = 0; m < 2; m++) {
        const uint32_t tb = m ? t2base : t1base;
        #pragma unroll
        for (int bb = 0; bb < 5; bb++) {
            const bool tr = (bb < r);
            const int aa = tr ? bb : r;
            const int bn = tr ? r : bb;
            const uint32_t tile = tb + (uint32_t)tri_idx(aa, bn) * TILE_BYTES;
            #pragma unroll
            for (int ks = 0; ks < 2; ks++) {
                if (tr) {
                    const uint32_t o = (uint32_t)ks * (16 * TILE_STRIDE_B) + lane_tr;
                    ldsm4t(fr[m][bb][ks][0][0], fr[m][bb][ks][0][1],
                           fr[m][bb][ks][0][2], fr[m][bb][ks][0][3], tile + o);
                    ldsm4t(fr[m][bb][ks][1][0], fr[m][bb][ks][1][1],
                           fr[m][bb][ks][1][2], fr[m][bb][ks][1][3], tile + o + 32);
                } else {
                    const uint32_t o = (uint32_t)ks * 32 + lane_nt;
                    ldsm4(fr[m][bb][ks][0][0], fr[m][bb][ks][0][1],
                          fr[m][bb][ks][0][2], fr[m][bb][ks][0][3], tile + o);
                    ldsm4(fr[m][bb][ks][1][0], fr[m][bb][ks][1][1],
                          fr[m][bb][ks][1][2], fr[m][bb][ks][1][3],
                          tile + o + 16 * TILE_STRIDE_B);
                }
            }
        }
    }

    // ---- replicated solver state (identical in every warp) ----
    float wv[8], mu_r[8];
    float tau = 0.0f;
    #pragma unroll
    for (int k = 0; k < 8; k++) {
        wv[k] = 1.0f / (float)N_SZ;
        mu_r[k] = mu[(size_t)b * N_SZ + lane + (k << 5)];
        const __half h = __float2half_rn(wv[k]);
        asm volatile("st.shared.u16 [%0], %1;"
                     :: "r"(wpriv + (uint32_t)k * 64 + lane_woff),
                        "h"(__half_as_ushort(h)) : "memory");
    }
    __syncwarp();
    __syncthreads();

    #pragma unroll 1
    for (int it = 0; it < N_ITERS; it++) {
        const uint32_t buf = (uint32_t)(it & 1);
        float* const y1s = (float*)(sm + SM_Y1 + buf * 1024);
        float* const y2s = (float*)(sm + SM_Y2 + buf * 1024);
        float* const prods = (float*)(sm + SM_PROD + buf * 32);

        float c1A[4] = {0.f,0.f,0.f,0.f}, c1B[4] = {0.f,0.f,0.f,0.f};
        uint32_t h2A[2] = {0u, 0u}, h2B[2] = {0u, 0u};   // G2 fp16 accumulators

        // ---- k-bands 0..4: register-resident fragments ----
        #pragma unroll
        for (int bb = 0; bb < 5; bb++) {
            #pragma unroll
            for (int ks = 0; ks < 2; ks++) {
                uint32_t b0, b1;
                const uint32_t waddr = wpriv + (uint32_t)((bb * 8 + ks * 4) * 8)
                                     + (uint32_t)(lane & 3) * 8;
                asm volatile("ld.shared.v2.b32 {%0,%1}, [%2];"
                             : "=r"(b0), "=r"(b1) : "r"(waddr));
                if (lane >= 4) { b0 = 0u; b1 = 0u; }

                mma16816(c1A, fr[0][bb][ks][0][0], fr[0][bb][ks][0][1],
                              fr[0][bb][ks][0][2], fr[0][bb][ks][0][3], b0, b1);
                mma16816(c1B, fr[0][bb][ks][1][0], fr[0][bb][ks][1][1],
                              fr[0][bb][ks][1][2], fr[0][bb][ks][1][3], b0, b1);
                mma16816h(h2A, fr[1][bb][ks][0][0], fr[1][bb][ks][0][1],
                               fr[1][bb][ks][0][2], fr[1][bb][ks][0][3], b0, b1);
                mma16816h(h2B, fr[1][bb][ks][1][0], fr[1][bb][ks][1][1],
                               fr[1][bb][ks][1][2], fr[1][bb][ks][1][3], b0, b1);
            }
        }

        // ---- k-bands 5..7: batched LDSM (4) then MMA (4) per (band,kslice) ----
        #pragma unroll
        for (int bb = 5; bb < 8; bb++) {
            const bool tr = (bb < r);
            const int aa = tr ? bb : r;
            const int bn = tr ? r : bb;
            const uint32_t toff = (uint32_t)tri_idx(aa, bn) * TILE_BYTES;
            const uint32_t tile1 = t1base + toff;
            const uint32_t tile2 = t2base + toff;
            #pragma unroll
            for (int ks = 0; ks < 2; ks++) {
                uint32_t b0, b1;
                const uint32_t waddr = wpriv + (uint32_t)((bb * 8 + ks * 4) * 8)
                                     + (uint32_t)(lane & 3) * 8;
                asm volatile("ld.shared.v2.b32 {%0,%1}, [%2];"
                             : "=r"(b0), "=r"(b1) : "r"(waddr));
                if (lane >= 4) { b0 = 0u; b1 = 0u; }

                uint32_t sA[4][4];
                if (tr) {
                    const uint32_t o = (uint32_t)ks * (16 * TILE_STRIDE_B) + lane_tr;
                    ldsm4t(sA[0][0], sA[0][1], sA[0][2], sA[0][3], tile1 + o);
                    ldsm4t(sA[1][0], sA[1][1], sA[1][2], sA[1][3], tile1 + o + 32);
                    ldsm4t(sA[2][0], sA[2][1], sA[2][2], sA[2][3], tile2 + o);
                    ldsm4t(sA[3][0], sA[3][1], sA[3][2], sA[3][3], tile2 + o + 32);
                } else {
                    const uint32_t o = (uint32_t)ks * 32 + lane_nt;
                    ldsm4(sA[0][0], sA[0][1], sA[0][2], sA[0][3], tile1 + o);
                    ldsm4(sA[1][0], sA[1][1], sA[1][2], sA[1][3],
                          tile1 + o + 16 * TILE_STRIDE_B);
                    ldsm4(sA[2][0], sA[2][1], sA[2][2], sA[2][3], tile2 + o);
                    ldsm4(sA[3][0], sA[3][1], sA[3][2], sA[3][3],
                          tile2 + o + 16 * TILE_STRIDE_B);
                }
                mma16816(c1A, sA[0][0], sA[0][1], sA[0][2], sA[0][3], b0, b1);
                mma16816(c1B, sA[1][0], sA[1][1], sA[1][2], sA[1][3], b0, b1);
                mma16816h(h2A, sA[2][0], sA[2][1], sA[2][2], sA[2][3], b0, b1);
                mma16816h(h2B, sA[3][0], sA[3][1], sA[3][2], sA[3][3], b0, b1);
            }
        }

        // ---- extract G2 results (col 0 = low half of each f16x2 pair) ----
        const float c2A0 = __low2float(*(const __half2*)&h2A[0]);
        const float c2A2 = __low2float(*(const __half2*)&h2A[1]);
        const float c2B0 = __low2float(*(const __half2*)&h2B[0]);
        const float c2B2 = __low2float(*(const __half2*)&h2B[1]);

        // ---- store y bands TRANSPOSED: y[c] -> float idx (c&31)*8 + (c>>5)
        const int g = lane >> 2;
        if ((lane & 3) == 0) {
            y1s[g * 8 + r]        = c1A[0];
            y1s[(g + 8) * 8 + r]  = c1A[2];
            y1s[(g + 16) * 8 + r] = c1B[0];
            y1s[(g + 24) * 8 + r] = c1B[2];
            y2s[g * 8 + r]        = c2A0;
            y2s[(g + 8) * 8 + r]  = c2A2;
            y2s[(g + 16) * 8 + r] = c2B0;
            y2s[(g + 24) * 8 + r] = c2B2;
        }
        {
            const float wg0 = __shfl_sync(0xFFFFFFFFu, wv[r], g);
            const float wg1 = __shfl_sync(0xFFFFFFFFu, wv[r], g + 8);
            const float wg2 = __shfl_sync(0xFFFFFFFFu, wv[r], g + 16);
            const float wg3 = __shfl_sync(0xFFFFFFFFu, wv[r], g + 24);
            float p = c2A0 * wg0 + c2A2 * wg1 + c2B0 * wg2 + c2B2 * wg3;
            p += __shfl_xor_sync(0xFFFFFFFFu, p, 4);
            p += __shfl_xor_sync(0xFFFFFFFFu, p, 8);
            p += __shfl_xor_sync(0xFFFFFFFFu, p, 16);
            if (lane == 0) prods[r] = p;
        }
        __syncthreads();   // the ONLY barrier per iteration

        // ---- replicated projection (vectorized reads) ----
        float4 pv0 = *(const float4*)prods;
        float4 pv1 = *(const float4*)(prods + 4);
        const float pr = ((pv0.x + pv0.y) + (pv0.z + pv0.w))
                       + ((pv1.x + pv1.y) + (pv1.z + pv1.w));
        const float nrm = sqrtf(fmaxf(pr, 1e-12f));
        const float kin = KAPPA / nrm;

        float y1v[8], y2v[8];
        {
            const float4 a0 = *(const float4*)(y1s + lane * 8);
            const float4 a1 = *(const float4*)(y1s + lane * 8 + 4);
            const float4 b0v = *(const float4*)(y2s + lane * 8);
            const float4 b1v = *(const float4*)(y2s + lane * 8 + 4);
            y1v[0] = a0.x; y1v[1] = a0.y; y1v[2] = a0.z; y1v[3] = a0.w;
            y1v[4] = a1.x; y1v[5] = a1.y; y1v[6] = a1.z; y1v[7] = a1.w;
            y2v[0] = b0v.x; y2v[1] = b0v.y; y2v[2] = b0v.z; y2v[3] = b0v.w;
            y2v[4] = b1v.x; y2v[5] = b1v.y; y2v[6] = b1v.z; y2v[7] = b1v.w;
        }

        float v[8];
        #pragma unroll
        for (int k = 0; k < 8; k++) {
            const float grad = -mu_r[k] + LAMBD * y1v[k] + kin * y2v[k];
            v[k] = wv[k] - step * grad;
        }

        // Warm-started Newton on f(tau) = sum(relu(v-tau)) - 1.
        float tt = tau;
        bool fb = false;
        for (int ni = 0; ni < 12; ni++) {
            float s = 0.f;
            int cnt = 0;
            #pragma unroll
            for (int k = 0; k < 8; k++) {
                const float d = v[k] - tt;
                if (d > 0.f) { s += d; cnt++; }
            }
            cnt = __reduce_add_sync(0xFFFFFFFFu, cnt);
            #pragma unroll
            for (int o = 16; o; o >>= 1)
                s += __shfl_xor_sync(0xFFFFFFFFu, s, o);
            if (cnt == 0) {
                if (fb) break;
                fb = true;
                float S = 0.f;
                #pragma unroll
                for (int k = 0; k < 8; k++) S += v[k];
                #pragma unroll
                for (int o = 16; o; o >>= 1)
                    S += __shfl_xor_sync(0xFFFFFFFFu, S, o);
                tt = (S - 1.0f) * (1.0f / (float)N_SZ);
                continue;
            }
            const float delta = (s - 1.0f) / (float)cnt;
            tt += delta;
            if (fabsf(delta) <= 1e-10f) break;
        }
        tau = tt;

        #pragma unroll
        for (int k = 0; k < 8; k++) {
            wv[k] = fmaxf(v[k] - tau, 0.f);
            const __half h = __float2half_rn(wv[k]);
            asm volatile("st.shared.u16 [%0], %1;"
                         :: "r"(wpriv + (uint32_t)k * 64 + lane_woff),
                            "h"(__half_as_ushort(h)) : "memory");
        }
        __syncwarp();
    }

    // ---- final clamp + renormalize (warp 0 writes) ----
    if (r == 0) {
        float s = 0.f;
        #pragma unroll
        for (int k = 0; k < 8; k++) { wv[k] = fmaxf(wv[k], 0.f); s += wv[k]; }
        #pragma unroll
        for (int o = 16; o; o >>= 1) s += __shfl_xor_sync(0xFFFFFFFFu, s, o);
        const float inv = 1.0f / (s + 1e-12f);
        #pragma unroll
        for (int k = 0; k < 8; k++)
            out[(size_t)b * N_SZ + lane + (k << 5)] = wv[k] * inv;
    }
}

// ---------------------------------------------------------------------------
// Launcher
// ---------------------------------------------------------------------------
extern "C" void kernel_launch(void* const* d_in, const int* in_sizes, int n_in,
                              void* d_out, int out_size) {
    const float* mu = (const float*)d_in[0];
    const float* U  = (const float*)d_in[1];
    const float* A  = (const float*)d_in[2];
    float* out = (float*)d_out;

    cudaFuncSetAttribute(syrk16_kernel, cudaFuncAttributeMaxDynamicSharedMemorySize,
                         SYRK_SMEM);
    cudaFuncSetAttribute(pgd_mma_kernel, cudaFuncAttributeMaxDynamicSharedMemorySize,
                         SM_TOTAL);

    syrk16_kernel<<<2 * B_SZ, 256, SYRK_SMEM>>>(U, A);
    pgd_mma_kernel<<<B_SZ, 256, SM_TOTAL>>>(mu, out);
}